// round 16
// baseline (speedup 1.0000x reference)
#include <cuda_runtime.h>
#include <cuda_fp16.h>
#include <math.h>
#include <stdint.h>

// Problem constants
#define N_TOK 2048
#define H_DIM 1024
#define E_NUM 8
#define F_DIM 1024
#define THRESHOLD 0.7f

// GEMM: CTA 128(M) x 256(N), K chunks of 32, 8 warps (warp tile 64x64), 4-stage cp.async
// Stage: AH 10240 + BH 20480 (pure fp16, single pass)
#define BUF_BYTES 30720
#define STAGES 4
#define SMEM_BYTES (BUF_BYTES * STAGES)   // 122880

// ---------------- device globals (scratch; no allocation allowed) ----------
__device__ __half g_xh[2097152];                      // x fp16
__device__ __half g_guph[16777216];                   // gate_up fp16
__device__ __half g_dph[8388608];                     // down fp16
__device__ __half g_midh[4194304];                    // mid fp16 (written by gu)
__device__ int    g_primary_mask;
__device__ int    g_top_i[N_TOK * 2];
__device__ float  g_top_w[N_TOK * 2];
__device__ int    g_tok_e[N_TOK * 2];
__device__ float  g_tok_w[N_TOK * 2];
__device__ int    g_list_tok[E_NUM][N_TOK];
__device__ float  g_list_w[E_NUM][N_TOK];
__device__ int    g_cnt[E_NUM], g_off[E_NUM];

// ---------------- helpers ----------------
__device__ __forceinline__ uint32_t smem_u32(const void* p) {
    uint32_t a;
    asm("{ .reg .u64 t; cvta.to.shared.u64 t, %1; cvt.u32.u64 %0, t; }" : "=r"(a) : "l"(p));
    return a;
}
__device__ __forceinline__ void ldm4(uint32_t* r, uint32_t addr) {
    asm volatile("ldmatrix.sync.aligned.m8n8.x4.shared.b16 {%0,%1,%2,%3}, [%4];"
                 : "=r"(r[0]), "=r"(r[1]), "=r"(r[2]), "=r"(r[3]) : "r"(addr));
}
__device__ __forceinline__ void mma16816(float* c, const uint32_t* a, const uint32_t* b) {
    asm volatile("mma.sync.aligned.m16n8k16.row.col.f32.f16.f16.f32 "
                 "{%0,%1,%2,%3}, {%4,%5,%6,%7}, {%8,%9}, {%0,%1,%2,%3};"
                 : "+f"(c[0]), "+f"(c[1]), "+f"(c[2]), "+f"(c[3])
                 : "r"(a[0]), "r"(a[1]), "r"(a[2]), "r"(a[3]), "r"(b[0]), "r"(b[1]));
}
__device__ __forceinline__ void cpasync16(uint32_t saddr, const void* g) {
    asm volatile("cp.async.cg.shared.global [%0], [%1], 16;" :: "r"(saddr), "l"(g) : "memory");
}
#define CP_COMMIT() asm volatile("cp.async.commit_group;" ::: "memory")
#define CP_WAIT2()  asm volatile("cp.async.wait_group 2;" ::: "memory")

__device__ __forceinline__ uint32_t pk(__half x, __half y) {
    __half2 t = __halves2half2(x, y);
    return *reinterpret_cast<uint32_t*>(&t);
}
// 8 floats -> packed fp16 (rn)
__device__ __forceinline__ uint4 cvt8h(float4 a, float4 b) {
    float f[8] = {a.x, a.y, a.z, a.w, b.x, b.y, b.z, b.w};
    __half h[8];
#pragma unroll
    for (int i = 0; i < 8; i++) h[i] = __float2half_rn(f[i]);
    return make_uint4(pk(h[0], h[1]), pk(h[2], h[3]), pk(h[4], h[5]), pk(h[6], h[7]));
}

// ---------------- prep: zero out + cvt x/gup/dp -> fp16 (fused) ----------
// blocks [0,1024): zero out ; [1024,2048): x ; [2048,10240): gup ; [10240,14336): dp
__global__ void prep_kernel(const float4* __restrict__ x,
                            const float4* __restrict__ gup,
                            const float4* __restrict__ dp,
                            float4* __restrict__ out) {
    int b = blockIdx.x;
    int t = threadIdx.x;
    if (b < 1024) {
        size_t i = (size_t)b * 256 + t;
        float4 z = make_float4(0.f, 0.f, 0.f, 0.f);
        out[2 * i] = z; out[2 * i + 1] = z;
        if (b == 0 && t == 0) g_primary_mask = 0;
    } else if (b < 2048) {
        size_t i = (size_t)(b - 1024) * 256 + t;
        ((uint4*)g_xh)[i] = cvt8h(x[2 * i], x[2 * i + 1]);
    } else if (b < 10240) {
        size_t i = (size_t)(b - 2048) * 256 + t;
        ((uint4*)g_guph)[i] = cvt8h(gup[2 * i], gup[2 * i + 1]);
    } else {
        size_t i = (size_t)(b - 10240) * 256 + t;
        ((uint4*)g_dph)[i] = cvt8h(dp[2 * i], dp[2 * i + 1]);
    }
}

// ---------------- router: grid 128 x 512 (16 tokens/block) ----------------
__global__ void router_kernel(const float* __restrict__ x,
                              const float* __restrict__ gw) {
    __shared__ __align__(16) float gws[E_NUM * H_DIM];
    int tid = threadIdx.x;
    for (int i = tid * 4; i < E_NUM * H_DIM; i += 2048)
        *(float4*)&gws[i] = *(const float4*)&gw[i];
    __syncthreads();

    int warp = tid >> 5, lane = tid & 31;
    int n = blockIdx.x * 16 + warp;
    const float* xp = x + (size_t)n * H_DIM;

    float acc[E_NUM];
#pragma unroll
    for (int e = 0; e < E_NUM; e++) acc[e] = 0.f;
    for (int h = lane * 4; h < H_DIM; h += 128) {
        float4 xv = *(const float4*)&xp[h];
#pragma unroll
        for (int e = 0; e < E_NUM; e++) {
            float4 wv = *(const float4*)&gws[e * H_DIM + h];
            acc[e] += xv.x * wv.x + xv.y * wv.y + xv.z * wv.z + xv.w * wv.w;
        }
    }
#pragma unroll
    for (int e = 0; e < E_NUM; e++)
#pragma unroll
        for (int o = 16; o; o >>= 1) acc[e] += __shfl_xor_sync(~0u, acc[e], o);

    if (lane == 0) {
        float m = acc[0];
#pragma unroll
        for (int e = 1; e < E_NUM; e++) m = fmaxf(m, acc[e]);
        float p[E_NUM];
#pragma unroll
        for (int e = 0; e < E_NUM; e++) p[e] = expf(acc[e] - m);
        int i0 = 0; float b0 = p[0];
#pragma unroll
        for (int e = 1; e < E_NUM; e++) if (p[e] > b0) { b0 = p[e]; i0 = e; }
        int i1 = -1; float b1 = -1.f;
#pragma unroll
        for (int e = 0; e < E_NUM; e++)
            if (e != i0 && p[e] > b1) { b1 = p[e]; i1 = e; }
        float s2 = b0 + b1;
        g_top_i[2 * n] = i0; g_top_i[2 * n + 1] = i1;
        g_top_w[2 * n] = b0 / s2; g_top_w[2 * n + 1] = b1 / s2;
        atomicOr(&g_primary_mask, 1 << i0);
    }
}

// ---------------- route: reroute + merge + compaction ----------------
__global__ void route_kernel(const float* __restrict__ sim) {
    __shared__ int map_s[E_NUM];
    __shared__ int cnt_s[E_NUM];
    int tid = threadIdx.x;
    int mask = g_primary_mask;

    if (tid < E_NUM) {
        int mp;
        if ((mask >> tid) & 1) {
            mp = tid;
        } else {
            float best = -1e30f; int bj = -1;
            for (int j = 0; j < E_NUM; j++)
                if ((mask >> j) & 1) {
                    float v = sim[tid * E_NUM + j];
                    if (v > best) { best = v; bj = j; }
                }
            mp = (bj >= 0 && best >= THRESHOLD) ? bj : tid;
        }
        map_s[tid] = mp;
    }
    __syncthreads();

    for (int n = tid; n < N_TOK; n += 256) {
        int i0 = g_top_i[2 * n], i1 = g_top_i[2 * n + 1];
        float w0 = g_top_w[2 * n], w1 = g_top_w[2 * n + 1];
        int e0 = map_s[i0], e1 = map_s[i1];
        if (e0 == e1) { w0 += w1; e1 = -1; }
        g_tok_e[2 * n] = e0; g_tok_e[2 * n + 1] = e1;
        g_tok_w[2 * n] = w0; g_tok_w[2 * n + 1] = w1;
    }
    __syncthreads();

    int warp = tid >> 5, lane = tid & 31;
    int e = warp;
    int cnt = 0;
    for (int base = 0; base < N_TOK; base += 32) {
        int n = base + lane;
        int e0 = g_tok_e[2 * n], e1 = g_tok_e[2 * n + 1];
        bool f0 = (e0 == e), f1 = (e1 == e);
        bool f = f0 || f1;
        float w = f0 ? g_tok_w[2 * n] : g_tok_w[2 * n + 1];
        unsigned b = __ballot_sync(~0u, f);
        if (f) {
            int pos = cnt + __popc(b & ((1u << lane) - 1));
            g_list_tok[e][pos] = n;
            g_list_w[e][pos] = w;
        }
        cnt += __popc(b);
    }
    if (lane == 0) cnt_s[e] = cnt;
    __syncthreads();
    if (tid == 0) {
        int o = 0;
        for (int i = 0; i < E_NUM; i++) { g_off[i] = o; g_cnt[i] = cnt_s[i]; o += cnt_s[i]; }
    }
}

// ---------------- grouped GEMM (IS_GU: x@gup^T + silu*u -> mid; else mid@dp^T -> +out)
// CTA 128M x 256N, 8 warps (2M x 4N of 64x64), K chunk 32, 4-stage cp.async, fp16,
// single __syncthreads per K chunk.
template<int IS_GU>
__global__ void __launch_bounds__(256, 1) gemm_mma(float* __restrict__ out) {
    int e = blockIdx.z;
    int cnt = g_cnt[e];
    int mbase = blockIdx.y * 128;
    if (mbase >= cnt) return;
    int nbx = blockIdx.x;
    int off = g_off[e];

    extern __shared__ char smem[];
    uint32_t sb = smem_u32(smem);
    int tid = threadIdx.x, w = tid >> 5, lid = tid & 31;

    // cp.async setup: per-thread 6 chunks of 16B per stage
    int rA0 = tid >> 2, seg = tid & 3;
    int sr0 = min(mbase + rA0, cnt - 1), sr1 = min(mbase + 64 + rA0, cnt - 1);
    const __half *Ah, *Bh;
    uint32_t gA0, gA1;
    if (IS_GU) {
        gA0 = (uint32_t)g_list_tok[e][sr0] * 1024 + seg * 8;
        gA1 = (uint32_t)g_list_tok[e][sr1] * 1024 + seg * 8;
        Ah = g_xh; Bh = g_guph;
    } else {
        gA0 = (uint32_t)(off + sr0) * 1024 + seg * 8;
        gA1 = (uint32_t)(off + sr1) * 1024 + seg * 8;
        Ah = g_midh; Bh = g_dph;
    }
    uint32_t gB[4];
#pragma unroll
    for (int j = 0; j < 4; j++) {
        int rB = j * 64 + rA0;
        int grow;
        if (IS_GU) grow = (rB < 128) ? (nbx * 128 + rB) : (1024 + nbx * 128 + (rB - 128));
        else       grow = nbx * 256 + rB;
        gB[j] = (uint32_t)(e * (IS_GU ? 2048 : 1024) + grow) * 1024 + seg * 8;
    }
    uint32_t sA0 = rA0 * 80 + seg * 16;
    uint32_t sA1 = sA0 + 64 * 80;
    uint32_t sBb = 10240 + rA0 * 80 + seg * 16;

    auto issue = [&](int kc) {
        uint32_t bo = sb + (uint32_t)(kc & 3) * BUF_BYTES;
        uint32_t ko = (uint32_t)kc * 32;
        cpasync16(bo + sA0, Ah + gA0 + ko);
        cpasync16(bo + sA1, Ah + gA1 + ko);
#pragma unroll
        for (int j = 0; j < 4; j++) cpasync16(bo + sBb + j * 5120, Bh + gB[j] + ko);
    };

    issue(0); CP_COMMIT();
    issue(1); CP_COMMIT();
    issue(2); CP_COMMIT();

    int wm = (w & 1) * 64, q = w >> 1;      // q: N quarter (0..3)
    int arow_l = lid & 15;
    int acol_l = (lid & 16) ? 8 : 0;
    int brow_l = (lid & 7) + ((lid & 16) ? 8 : 0);
    int bcol_l = (lid & 8) ? 8 : 0;

    float c[4][8][4];
#pragma unroll
    for (int i = 0; i < 4; i++)
#pragma unroll
        for (int j = 0; j < 8; j++)
#pragma unroll
            for (int k = 0; k < 4; k++) c[i][j][k] = 0.f;

    for (int kc = 0; kc < 32; kc++) {
        CP_WAIT2();            // own groups: waits until group kc complete
        __syncthreads();       // all warps' stage-kc data visible; buf (kc+3)&3 free
        if (kc + 3 < 32) issue(kc + 3);
        CP_COMMIT();
        uint32_t bufb = sb + (uint32_t)(kc & 3) * BUF_BYTES;
#pragma unroll
        for (int ks = 0; ks < 32; ks += 16) {
            uint32_t bh[16];
            uint32_t ba = bufb + 10240 + 2 * ((q * 64 + brow_l) * 40 + ks + bcol_l);
#pragma unroll
            for (int j = 0; j < 4; j++) ldm4(bh + j * 4, ba + j * 16 * 80);
#pragma unroll
            for (int mt = 0; mt < 4; mt++) {
                uint32_t aa = bufb + 2 * ((wm + mt * 16 + arow_l) * 40 + ks + acol_l);
                uint32_t ah[4];
                ldm4(ah, aa);
#pragma unroll
                for (int nn = 0; nn < 8; nn++) mma16816(c[mt][nn], ah, &bh[(nn >> 1) * 4 + (nn & 1) * 2]);
            }
        }
    }

    if (IS_GU) {
        // N cols 0..127 = gate (q 0,1), 128..255 = up (q 2,3); exchange u via smem
        // su spans bytes [0, 67584) = buffers 0-2; last compute reads buffer 3 -> no overlap
        float* su = (float*)smem;           // [128][132]
        const int LDU = 132;
        if (q >= 2) {
#pragma unroll
            for (int mt = 0; mt < 4; mt++)
#pragma unroll
                for (int nn = 0; nn < 8; nn++) {
                    int r = wm + mt * 16 + (lid >> 2);
                    int col = (q - 2) * 64 + nn * 8 + (lid & 3) * 2;
                    *(float2*)&su[r * LDU + col] = make_float2(c[mt][nn][0], c[mt][nn][1]);
                    *(float2*)&su[(r + 8) * LDU + col] = make_float2(c[mt][nn][2], c[mt][nn][3]);
                }
        }
        __syncthreads();
        if (q < 2) {
#pragma unroll
            for (int mt = 0; mt < 4; mt++)
#pragma unroll
                for (int nn = 0; nn < 8; nn++) {
                    int r0 = wm + mt * 16 + (lid >> 2);
                    int col = q * 64 + nn * 8 + (lid & 3) * 2;
#pragma unroll
                    for (int hf = 0; hf < 2; hf++) {
                        int r = r0 + hf * 8;
                        int m = mbase + r;
                        if (m < cnt) {
                            float2 u = *(float2*)&su[r * LDU + col];
                            float g0 = c[mt][nn][hf * 2 + 0];
                            float g1 = c[mt][nn][hf * 2 + 1];
                            float v0 = (g0 / (1.f + expf(-g0))) * u.x;
                            float v1 = (g1 / (1.f + expf(-g1))) * u.y;
                            size_t o = (size_t)(off + m) * F_DIM + nbx * 128 + col;
                            *(__half2*)&g_midh[o] = __halves2half2(
                                __float2half_rn(v0), __float2half_rn(v1));
                        }
                    }
                }
        }
    } else {
        // down: weighted atomic scatter into out. Each element gets <=2 adds;
        // fp add of two terms onto 0 is commutative-exact -> deterministic.
        int hb = nbx * 256;
#pragma unroll
        for (int mt = 0; mt < 4; mt++)
#pragma unroll
            for (int nn = 0; nn < 8; nn++) {
                int r0 = wm + mt * 16 + (lid >> 2);
                int col = q * 64 + nn * 8 + (lid & 3) * 2;
#pragma unroll
                for (int hf = 0; hf < 2; hf++) {
                    int m = mbase + r0 + hf * 8;
                    if (m < cnt) {
                        int tok = g_list_tok[e][m];
                        float wgt = g_list_w[e][m];
                        float* op = out + (size_t)tok * H_DIM + hb + col;
                        atomicAdd(op + 0, wgt * c[mt][nn][hf * 2 + 0]);
                        atomicAdd(op + 1, wgt * c[mt][nn][hf * 2 + 1]);
                    }
                }
            }
    }
}

// ---------------- launch ----------------
extern "C" void kernel_launch(void* const* d_in, const int* in_sizes, int n_in,
                              void* d_out, int out_size) {
    const float* x   = (const float*)d_in[0];
    const float* gw  = (const float*)d_in[1];
    const float* gup = (const float*)d_in[2];
    const float* dp  = (const float*)d_in[3];
    const float* sim = (const float*)d_in[4];
    float* out = (float*)d_out;

    cudaFuncSetAttribute(gemm_mma<1>, cudaFuncAttributeMaxDynamicSharedMemorySize, SMEM_BYTES);
    cudaFuncSetAttribute(gemm_mma<0>, cudaFuncAttributeMaxDynamicSharedMemorySize, SMEM_BYTES);

    prep_kernel<<<14336, 256>>>((const float4*)x, (const float4*)gup,
                                (const float4*)dp, (float4*)out);
    router_kernel<<<128, 512>>>(x, gw);
    route_kernel<<<1, 256>>>(sim);
    gemm_mma<1><<<dim3(8, 16, 8), 256, SMEM_BYTES>>>(out);   // gate_up + silu*u
    gemm_mma<0><<<dim3(4, 16, 8), 256, SMEM_BYTES>>>(out);   // down + weighted scatter
}

// round 17
// speedup vs baseline: 1.3629x; 1.3629x over previous
#include <cuda_runtime.h>
#include <cuda_fp16.h>
#include <math.h>
#include <stdint.h>

// Problem constants
#define N_TOK 2048
#define H_DIM 1024
#define E_NUM 8
#define F_DIM 1024
#define THRESHOLD 0.7f

// GEMM: CTA 128(M) x 256(N), K chunks of 32, 8 warps (warp tile 64x64), 4-stage cp.async
// Stage: AH 10240 + BH 20480 (pure fp16, single pass)
#define BUF_BYTES 30720
#define STAGES 4
#define SMEM_BYTES (BUF_BYTES * STAGES)   // 122880

// ---------------- device globals (scratch; no allocation allowed) ----------
__device__ __half g_xh[2097152];                      // x fp16
__device__ __half g_guph[16777216];                   // gate_up fp16
__device__ __half g_dph[8388608];                     // down fp16
__device__ __half g_midh[4194304];                    // mid fp16 (written by gu)
__device__ float  g_y[4194304];                       // per-slot down output
__device__ int    g_primary_mask;
__device__ int    g_top_i[N_TOK * 2];
__device__ float  g_top_w[N_TOK * 2];
__device__ int    g_tok_e[N_TOK * 2];
__device__ float  g_tok_w[N_TOK * 2];
__device__ int    g_list_tok[E_NUM][N_TOK];
__device__ float  g_list_w[E_NUM][N_TOK];
__device__ int    g_cnt[E_NUM], g_off[E_NUM];
__device__ int    g_nslot[N_TOK];
__device__ int    g_slot[N_TOK * 2];
__device__ float  g_wslot[N_TOK * 2];

// ---------------- helpers ----------------
__device__ __forceinline__ uint32_t smem_u32(const void* p) {
    uint32_t a;
    asm("{ .reg .u64 t; cvta.to.shared.u64 t, %1; cvt.u32.u64 %0, t; }" : "=r"(a) : "l"(p));
    return a;
}
__device__ __forceinline__ void ldm4(uint32_t* r, uint32_t addr) {
    asm volatile("ldmatrix.sync.aligned.m8n8.x4.shared.b16 {%0,%1,%2,%3}, [%4];"
                 : "=r"(r[0]), "=r"(r[1]), "=r"(r[2]), "=r"(r[3]) : "r"(addr));
}
__device__ __forceinline__ void mma16816(float* c, const uint32_t* a, const uint32_t* b) {
    asm volatile("mma.sync.aligned.m16n8k16.row.col.f32.f16.f16.f32 "
                 "{%0,%1,%2,%3}, {%4,%5,%6,%7}, {%8,%9}, {%0,%1,%2,%3};"
                 : "+f"(c[0]), "+f"(c[1]), "+f"(c[2]), "+f"(c[3])
                 : "r"(a[0]), "r"(a[1]), "r"(a[2]), "r"(a[3]), "r"(b[0]), "r"(b[1]));
}
__device__ __forceinline__ void cpasync16(uint32_t saddr, const void* g) {
    asm volatile("cp.async.cg.shared.global [%0], [%1], 16;" :: "r"(saddr), "l"(g) : "memory");
}
#define CP_COMMIT() asm volatile("cp.async.commit_group;" ::: "memory")
#define CP_WAIT3()  asm volatile("cp.async.wait_group 3;" ::: "memory")

__device__ __forceinline__ uint32_t pk(__half x, __half y) {
    __half2 t = __halves2half2(x, y);
    return *reinterpret_cast<uint32_t*>(&t);
}
// 8 floats -> packed fp16 (rn)
__device__ __forceinline__ uint4 cvt8h(float4 a, float4 b) {
    float f[8] = {a.x, a.y, a.z, a.w, b.x, b.y, b.z, b.w};
    __half h[8];
#pragma unroll
    for (int i = 0; i < 8; i++) h[i] = __float2half_rn(f[i]);
    return make_uint4(pk(h[0], h[1]), pk(h[2], h[3]), pk(h[4], h[5]), pk(h[6], h[7]));
}

// ---------------- prep: cvt x/gup/dp -> fp16 (fused, 3 ranges) ----------
// blocks [0,1024): x ; [1024,9216): gup ; [9216,13312): dp
__global__ void prep_kernel(const float4* __restrict__ x,
                            const float4* __restrict__ gup,
                            const float4* __restrict__ dp) {
    int b = blockIdx.x;
    int t = threadIdx.x;
    if (b < 1024) {
        size_t i = (size_t)b * 256 + t;
        ((uint4*)g_xh)[i] = cvt8h(x[2 * i], x[2 * i + 1]);
        if (b == 0 && t == 0) g_primary_mask = 0;
    } else if (b < 9216) {
        size_t i = (size_t)(b - 1024) * 256 + t;
        ((uint4*)g_guph)[i] = cvt8h(gup[2 * i], gup[2 * i + 1]);
    } else {
        size_t i = (size_t)(b - 9216) * 256 + t;
        ((uint4*)g_dph)[i] = cvt8h(dp[2 * i], dp[2 * i + 1]);
    }
}

// ---------------- router: grid 128 x 512 (16 tokens/block), h-loop unrolled ---
__global__ void router_kernel(const float* __restrict__ x,
                              const float* __restrict__ gw) {
    __shared__ __align__(16) float gws[E_NUM * H_DIM];
    int tid = threadIdx.x;
    for (int i = tid * 4; i < E_NUM * H_DIM; i += 2048)
        *(float4*)&gws[i] = *(const float4*)&gw[i];
    __syncthreads();

    int warp = tid >> 5, lane = tid & 31;
    int n = blockIdx.x * 16 + warp;
    const float* xp = x + (size_t)n * H_DIM;

    float acc[E_NUM];
#pragma unroll
    for (int e = 0; e < E_NUM; e++) acc[e] = 0.f;
    // 2 independent float4 loads in flight per iteration (MLP boost)
    for (int h = lane * 4; h < H_DIM; h += 256) {
        float4 xv0 = *(const float4*)&xp[h];
        float4 xv1 = *(const float4*)&xp[h + 128];
#pragma unroll
        for (int e = 0; e < E_NUM; e++) {
            float4 w0 = *(const float4*)&gws[e * H_DIM + h];
            float4 w1 = *(const float4*)&gws[e * H_DIM + h + 128];
            acc[e] += xv0.x * w0.x + xv0.y * w0.y + xv0.z * w0.z + xv0.w * w0.w
                    + xv1.x * w1.x + xv1.y * w1.y + xv1.z * w1.z + xv1.w * w1.w;
        }
    }
#pragma unroll
    for (int e = 0; e < E_NUM; e++)
#pragma unroll
        for (int o = 16; o; o >>= 1) acc[e] += __shfl_xor_sync(~0u, acc[e], o);

    if (lane == 0) {
        float m = acc[0];
#pragma unroll
        for (int e = 1; e < E_NUM; e++) m = fmaxf(m, acc[e]);
        float p[E_NUM];
#pragma unroll
        for (int e = 0; e < E_NUM; e++) p[e] = expf(acc[e] - m);
        int i0 = 0; float b0 = p[0];
#pragma unroll
        for (int e = 1; e < E_NUM; e++) if (p[e] > b0) { b0 = p[e]; i0 = e; }
        int i1 = -1; float b1 = -1.f;
#pragma unroll
        for (int e = 0; e < E_NUM; e++)
            if (e != i0 && p[e] > b1) { b1 = p[e]; i1 = e; }
        float s2 = b0 + b1;
        g_top_i[2 * n] = i0; g_top_i[2 * n + 1] = i1;
        g_top_w[2 * n] = b0 / s2; g_top_w[2 * n + 1] = b1 / s2;
        atomicOr(&g_primary_mask, 1 << i0);
    }
}

// ---------------- route: reroute + merge + compaction + slot map ---------
__global__ void route_kernel(const float* __restrict__ sim) {
    __shared__ int map_s[E_NUM];
    __shared__ int cnt_s[E_NUM];
    int tid = threadIdx.x;
    int mask = g_primary_mask;

    for (int n = tid; n < N_TOK; n += 256) g_nslot[n] = 0;

    if (tid < E_NUM) {
        int mp;
        if ((mask >> tid) & 1) {
            mp = tid;
        } else {
            float best = -1e30f; int bj = -1;
            for (int j = 0; j < E_NUM; j++)
                if ((mask >> j) & 1) {
                    float v = sim[tid * E_NUM + j];
                    if (v > best) { best = v; bj = j; }
                }
            mp = (bj >= 0 && best >= THRESHOLD) ? bj : tid;
        }
        map_s[tid] = mp;
    }
    __syncthreads();

    for (int n = tid; n < N_TOK; n += 256) {
        int i0 = g_top_i[2 * n], i1 = g_top_i[2 * n + 1];
        float w0 = g_top_w[2 * n], w1 = g_top_w[2 * n + 1];
        int e0 = map_s[i0], e1 = map_s[i1];
        if (e0 == e1) { w0 += w1; e1 = -1; }
        g_tok_e[2 * n] = e0; g_tok_e[2 * n + 1] = e1;
        g_tok_w[2 * n] = w0; g_tok_w[2 * n + 1] = w1;
    }
    __syncthreads();

    int warp = tid >> 5, lane = tid & 31;
    int e = warp;
    int cnt = 0;
    for (int base = 0; base < N_TOK; base += 32) {
        int n = base + lane;
        int e0 = g_tok_e[2 * n], e1 = g_tok_e[2 * n + 1];
        bool f0 = (e0 == e), f1 = (e1 == e);
        bool f = f0 || f1;
        float w = f0 ? g_tok_w[2 * n] : g_tok_w[2 * n + 1];
        unsigned b = __ballot_sync(~0u, f);
        if (f) {
            int pos = cnt + __popc(b & ((1u << lane) - 1));
            g_list_tok[e][pos] = n;
            g_list_w[e][pos] = w;
        }
        cnt += __popc(b);
    }
    if (lane == 0) cnt_s[e] = cnt;
    __syncthreads();
    if (tid == 0) {
        int o = 0;
        for (int i = 0; i < E_NUM; i++) { g_off[i] = o; g_cnt[i] = cnt_s[i]; o += cnt_s[i]; }
    }
    __syncthreads();
    // invert lists -> per-token slot map (order-independent: combine add commutes)
    for (int pos = lane; pos < cnt_s[e]; pos += 32) {
        int slot = g_off[e] + pos;
        int tok = g_list_tok[e][pos];
        int idx = atomicAdd(&g_nslot[tok], 1);
        g_slot[2 * tok + idx] = slot;
        g_wslot[2 * tok + idx] = g_list_w[e][pos];
    }
}

// ---------------- grouped GEMM (IS_GU: x@gup^T + silu*u -> mid; else mid@dp^T -> y)
// CTA 128M x 256N, 8 warps (2M x 4N of 64x64), K chunk 32, 4-stage cp.async, pure fp16
// R12 pipeline ordering: issue -> commit -> wait3 -> sync -> compute -> sync
template<int IS_GU>
__global__ void __launch_bounds__(256, 1) gemm_mma() {
    int e = blockIdx.z;
    int cnt = g_cnt[e];
    int mbase = blockIdx.y * 128;
    if (mbase >= cnt) return;
    int nbx = blockIdx.x;
    int off = g_off[e];

    extern __shared__ char smem[];
    uint32_t sb = smem_u32(smem);
    int tid = threadIdx.x, w = tid >> 5, lid = tid & 31;

    // cp.async setup: per-thread 6 chunks of 16B per stage
    int rA0 = tid >> 2, seg = tid & 3;
    int sr0 = min(mbase + rA0, cnt - 1), sr1 = min(mbase + 64 + rA0, cnt - 1);
    const __half *Ah, *Bh;
    uint32_t gA0, gA1;
    if (IS_GU) {
        gA0 = (uint32_t)g_list_tok[e][sr0] * 1024 + seg * 8;
        gA1 = (uint32_t)g_list_tok[e][sr1] * 1024 + seg * 8;
        Ah = g_xh; Bh = g_guph;
    } else {
        gA0 = (uint32_t)(off + sr0) * 1024 + seg * 8;
        gA1 = (uint32_t)(off + sr1) * 1024 + seg * 8;
        Ah = g_midh; Bh = g_dph;
    }
    uint32_t gB[4];
#pragma unroll
    for (int j = 0; j < 4; j++) {
        int rB = j * 64 + rA0;
        int grow;
        if (IS_GU) grow = (rB < 128) ? (nbx * 128 + rB) : (1024 + nbx * 128 + (rB - 128));
        else       grow = nbx * 256 + rB;
        gB[j] = (uint32_t)(e * (IS_GU ? 2048 : 1024) + grow) * 1024 + seg * 8;
    }
    uint32_t sA0 = rA0 * 80 + seg * 16;
    uint32_t sA1 = sA0 + 64 * 80;
    uint32_t sBb = 10240 + rA0 * 80 + seg * 16;

    auto issue = [&](int kc) {
        uint32_t bo = sb + (uint32_t)(kc & 3) * BUF_BYTES;
        uint32_t ko = (uint32_t)kc * 32;
        cpasync16(bo + sA0, Ah + gA0 + ko);
        cpasync16(bo + sA1, Ah + gA1 + ko);
#pragma unroll
        for (int j = 0; j < 4; j++) cpasync16(bo + sBb + j * 5120, Bh + gB[j] + ko);
    };

    issue(0); CP_COMMIT();
    issue(1); CP_COMMIT();
    issue(2); CP_COMMIT();

    int wm = (w & 1) * 64, q = w >> 1;      // q: N quarter (0..3)
    int arow_l = lid & 15;
    int acol_l = (lid & 16) ? 8 : 0;
    int brow_l = (lid & 7) + ((lid & 16) ? 8 : 0);
    int bcol_l = (lid & 8) ? 8 : 0;

    float c[4][8][4];
#pragma unroll
    for (int i = 0; i < 4; i++)
#pragma unroll
        for (int j = 0; j < 8; j++)
#pragma unroll
            for (int k = 0; k < 4; k++) c[i][j][k] = 0.f;

    for (int kc = 0; kc < 32; kc++) {
        if (kc + 3 < 32) issue(kc + 3);
        CP_COMMIT();
        CP_WAIT3();
        __syncthreads();
        uint32_t bufb = sb + (uint32_t)(kc & 3) * BUF_BYTES;
#pragma unroll
        for (int ks = 0; ks < 32; ks += 16) {
            uint32_t bh[16];
            uint32_t ba = bufb + 10240 + 2 * ((q * 64 + brow_l) * 40 + ks + bcol_l);
#pragma unroll
            for (int j = 0; j < 4; j++) ldm4(bh + j * 4, ba + j * 16 * 80);
#pragma unroll
            for (int mt = 0; mt < 4; mt++) {
                uint32_t aa = bufb + 2 * ((wm + mt * 16 + arow_l) * 40 + ks + acol_l);
                uint32_t ah[4];
                ldm4(ah, aa);
#pragma unroll
                for (int nn = 0; nn < 8; nn++) mma16816(c[mt][nn], ah, &bh[(nn >> 1) * 4 + (nn & 1) * 2]);
            }
        }
        __syncthreads();
    }

    if (IS_GU) {
        // N cols 0..127 = gate (q 0,1), 128..255 = up (q 2,3); exchange u via smem
        float* su = (float*)smem;           // [128][132]
        const int LDU = 132;
        if (q >= 2) {
#pragma unroll
            for (int mt = 0; mt < 4; mt++)
#pragma unroll
                for (int nn = 0; nn < 8; nn++) {
                    int r = wm + mt * 16 + (lid >> 2);
                    int col = (q - 2) * 64 + nn * 8 + (lid & 3) * 2;
                    *(float2*)&su[r * LDU + col] = make_float2(c[mt][nn][0], c[mt][nn][1]);
                    *(float2*)&su[(r + 8) * LDU + col] = make_float2(c[mt][nn][2], c[mt][nn][3]);
                }
        }
        __syncthreads();
        if (q < 2) {
#pragma unroll
            for (int mt = 0; mt < 4; mt++)
#pragma unroll
                for (int nn = 0; nn < 8; nn++) {
                    int r0 = wm + mt * 16 + (lid >> 2);
                    int col = q * 64 + nn * 8 + (lid & 3) * 2;
#pragma unroll
                    for (int hf = 0; hf < 2; hf++) {
                        int r = r0 + hf * 8;
                        int m = mbase + r;
                        if (m < cnt) {
                            float2 u = *(float2*)&su[r * LDU + col];
                            float g0 = c[mt][nn][hf * 2 + 0];
                            float g1 = c[mt][nn][hf * 2 + 1];
                            float v0 = (g0 / (1.f + expf(-g0))) * u.x;
                            float v1 = (g1 / (1.f + expf(-g1))) * u.y;
                            size_t o = (size_t)(off + m) * F_DIM + nbx * 128 + col;
                            *(__half2*)&g_midh[o] = __halves2half2(
                                __float2half_rn(v0), __float2half_rn(v1));
                        }
                    }
                }
        }
    } else {
        // down: write per-slot result (no atomics; combine applies weights)
        int hb = nbx * 256;
#pragma unroll
        for (int mt = 0; mt < 4; mt++)
#pragma unroll
            for (int nn = 0; nn < 8; nn++) {
                int r0 = wm + mt * 16 + (lid >> 2);
                int col = q * 64 + nn * 8 + (lid & 3) * 2;
#pragma unroll
                for (int hf = 0; hf < 2; hf++) {
                    int m = mbase + r0 + hf * 8;
                    if (m < cnt) {
                        size_t o = (size_t)(off + m) * H_DIM + hb + col;
                        *(float2*)&g_y[o] = make_float2(c[mt][nn][hf * 2 + 0], c[mt][nn][hf * 2 + 1]);
                    }
                }
            }
    }
}

// ---------------- combine: out[tok] = sum_slots w * y[slot] ----------------
__global__ void combine_kernel(float* __restrict__ out) {
    int n = blockIdx.x;
    int h = threadIdx.x * 4;
    int ns = g_nslot[n];
    int s0 = g_slot[2 * n]; float w0 = g_wslot[2 * n];
    float4 y0 = *(const float4*)&g_y[(size_t)s0 * H_DIM + h];
    float4 r = make_float4(w0 * y0.x, w0 * y0.y, w0 * y0.z, w0 * y0.w);
    if (ns > 1) {
        int s1 = g_slot[2 * n + 1]; float w1 = g_wslot[2 * n + 1];
        float4 y1 = *(const float4*)&g_y[(size_t)s1 * H_DIM + h];
        r.x += w1 * y1.x; r.y += w1 * y1.y; r.z += w1 * y1.z; r.w += w1 * y1.w;
    }
    *(float4*)&out[(size_t)n * H_DIM + h] = r;
}

// ---------------- launch ----------------
extern "C" void kernel_launch(void* const* d_in, const int* in_sizes, int n_in,
                              void* d_out, int out_size) {
    const float* x   = (const float*)d_in[0];
    const float* gw  = (const float*)d_in[1];
    const float* gup = (const float*)d_in[2];
    const float* dp  = (const float*)d_in[3];
    const float* sim = (const float*)d_in[4];
    float* out = (float*)d_out;

    cudaFuncSetAttribute(gemm_mma<1>, cudaFuncAttributeMaxDynamicSharedMemorySize, SMEM_BYTES);
    cudaFuncSetAttribute(gemm_mma<0>, cudaFuncAttributeMaxDynamicSharedMemorySize, SMEM_BYTES);

    prep_kernel<<<13312, 256>>>((const float4*)x, (const float4*)gup, (const float4*)dp);
    router_kernel<<<128, 512>>>(x, gw);
    route_kernel<<<1, 256>>>(sim);
    gemm_mma<1><<<dim3(8, 16, 8), 256, SMEM_BYTES>>>();   // gate_up + silu*u
    gemm_mma<0><<<dim3(4, 16, 8), 256, SMEM_BYTES>>>();   // down -> y slots
    combine_kernel<<<N_TOK, 256>>>(out);
}